// round 1
// baseline (speedup 1.0000x reference)
#include <cuda_runtime.h>
#include <cuda_bf16.h>

// Blocked affine-scan RK4 integrator.
// The RK4 step of this linear system is exactly x_{t+1} = A x_t + B u_t
// (state x = [y1, y2, v1, v2]). We exploit associativity of affine maps:
//   setup:  derive A (4x4), B (4x2) in fp64 via basis probing, and A^L.
//   phase1: per-chunk drive vectors d_c (parallel).
//   phase2: serial scan over chunk boundaries (313 iters, 1 thread).
//   phase3: per-chunk replay writing outputs (parallel).

#define L_CHUNK 320
#define MAX_CHUNKS 1024

__device__ float g_A[16];
__device__ float g_B[8];
__device__ float g_AL[16];
__device__ float g_cd[MAX_CHUNKS][4];   // per-chunk drive vector (state from zero IC)
__device__ float g_cx[MAX_CHUNKS][4];   // chunk start states

// ---------------------------------------------------------------------------
// Double-precision RK4 step (matches reference structure); linear in (state,u)
// ---------------------------------------------------------------------------
struct DSys {
    double Cm[4], Km[4], M[2], dt;
};

__device__ void dstep(const DSys& m, double s[4], const double u[2]) {
    const double dt = m.dt;
    double y0 = s[0], y1 = s[1], v0 = s[2], v1 = s[3];

#define ACC(z0, z1, w0, w1, a0, a1)                                             \
    a0 = (u[0] - (m.Cm[0]*(w0) + m.Cm[1]*(w1)) - (m.Km[0]*(z0) + m.Km[1]*(z1))) / m.M[0]; \
    a1 = (u[1] - (m.Cm[2]*(w0) + m.Cm[3]*(w1)) - (m.Km[2]*(z0) + m.Km[3]*(z1))) / m.M[1];

    double k1a, k1b; ACC(y0, y1, v0, v1, k1a, k1b);
    double y2a = y0 + v0*dt*0.5, y2b = y1 + v1*dt*0.5;
    double v2a = v0 + k1a*dt*0.5, v2b = v1 + k1b*dt*0.5;
    double k2a, k2b; ACC(y2a, y2b, v2a, v2b, k2a, k2b);
    double y3a = y0 + v2a*dt*0.5, y3b = y1 + v2b*dt*0.5;
    double v3a = v0 + k2a*dt*0.5, v3b = v1 + k2b*dt*0.5;
    double k3a, k3b; ACC(y3a, y3b, v3a, v3b, k3a, k3b);
    double y4a = y0 + v3a*dt, y4b = y1 + v3b*dt;
    double v4a = v0 + k3a*dt, v4b = v1 + k3b*dt;
    double k4a, k4b; ACC(y4a, y4b, v4a, v4b, k4a, k4b);
    (void)y2a; (void)y2b; (void)y3a; (void)y3b; (void)y4a; (void)y4b;

    s[0] = y0 + dt/6.0 * (v0 + 2.0*v2a + 2.0*v3a + v4a);
    s[1] = y1 + dt/6.0 * (v1 + 2.0*v2b + 2.0*v3b + v4b);
    s[2] = v0 + dt/6.0 * (k1a + 2.0*k2a + 2.0*k3a + k4a);
    s[3] = v1 + dt/6.0 * (k1b + 2.0*k2b + 2.0*k3b + k4b);
#undef ACC
}

__device__ void dmatmul4(double* __restrict__ R,
                         const double* __restrict__ P,
                         const double* __restrict__ Q) {
    for (int i = 0; i < 4; i++)
        for (int j = 0; j < 4; j++) {
            double s = 0.0;
            for (int k = 0; k < 4; k++) s += P[i*4+k] * Q[k*4+j];
            R[i*4+j] = s;
        }
}

// ---------------------------------------------------------------------------
// Setup: derive A, B via basis probing; A^L via binary exponentiation (fp64)
// ---------------------------------------------------------------------------
__global__ void setup_kernel(const float* __restrict__ M,
                             const float* __restrict__ C,
                             const float* __restrict__ K,
                             const float* __restrict__ x0,
                             const float* __restrict__ dtp,
                             int L) {
    DSys m;
    m.M[0] = (double)M[0]; m.M[1] = (double)M[1];
    double C0 = C[0], C1 = C[1], C2 = C[2];
    m.Cm[0] = C0 + C1; m.Cm[1] = -C1; m.Cm[2] = -C1; m.Cm[3] = C2 + C1;
    double K0 = K[0], K1 = K[1], K2 = K[2];
    m.Km[0] = K0 + K1; m.Km[1] = -K1; m.Km[2] = -K1; m.Km[3] = K2 + K1;
    m.dt = (double)dtp[0];

    double A[16], B[8];
    for (int j = 0; j < 4; j++) {          // A columns: step(e_j, u=0)
        double s[4] = {0, 0, 0, 0}; s[j] = 1.0;
        double u[2] = {0, 0};
        dstep(m, s, u);
        for (int i = 0; i < 4; i++) A[i*4+j] = s[i];
    }
    for (int j = 0; j < 2; j++) {          // B columns: step(0, u=e_j)
        double s[4] = {0, 0, 0, 0};
        double u[2] = {0, 0}; u[j] = 1.0;
        dstep(m, s, u);
        for (int i = 0; i < 2; i++) { }
        for (int i = 0; i < 4; i++) B[i*2+j] = s[i];
    }

    // A^L by binary exponentiation
    double P[16], Q[16], R[16];
    for (int i = 0; i < 16; i++) { P[i] = 0.0; Q[i] = A[i]; }
    P[0] = P[5] = P[10] = P[15] = 1.0;
    int e = L;
    while (e) {
        if (e & 1) { dmatmul4(R, P, Q); for (int i = 0; i < 16; i++) P[i] = R[i]; }
        e >>= 1;
        if (e) { dmatmul4(R, Q, Q); for (int i = 0; i < 16; i++) Q[i] = R[i]; }
    }

    for (int i = 0; i < 16; i++) { g_A[i] = (float)A[i]; g_AL[i] = (float)P[i]; }
    for (int i = 0; i < 8;  i++) g_B[i] = (float)B[i];

    // Initial state: x0 layout is [y1, v1, y2, v2]; our state is [y1, y2, v1, v2]
    g_cx[0][0] = x0[0];
    g_cx[0][1] = x0[2];
    g_cx[0][2] = x0[1];
    g_cx[0][3] = x0[3];
}

// ---------------------------------------------------------------------------
// One affine iteration x <- A x + B u, tree-reduced for short dependency chain
// ---------------------------------------------------------------------------
#define AFFINE_STEP(A, B, ux, uy, x0_, x1_, x2_, x3_)                          \
    do {                                                                       \
        float r0 = fmaf((B)[0], (ux), (B)[1] * (uy));                          \
        float r1 = fmaf((B)[2], (ux), (B)[3] * (uy));                          \
        float r2 = fmaf((B)[4], (ux), (B)[5] * (uy));                          \
        float r3 = fmaf((B)[6], (ux), (B)[7] * (uy));                          \
        float n0 = fmaf((A)[0],  (x0_), (A)[1]  * (x1_)) +                     \
                   fmaf((A)[2],  (x2_), fmaf((A)[3],  (x3_), r0));             \
        float n1 = fmaf((A)[4],  (x0_), (A)[5]  * (x1_)) +                     \
                   fmaf((A)[6],  (x2_), fmaf((A)[7],  (x3_), r1));             \
        float n2 = fmaf((A)[8],  (x0_), (A)[9]  * (x1_)) +                     \
                   fmaf((A)[10], (x2_), fmaf((A)[11], (x3_), r2));             \
        float n3 = fmaf((A)[12], (x0_), (A)[13] * (x1_)) +                     \
                   fmaf((A)[14], (x2_), fmaf((A)[15], (x3_), r3));             \
        (x0_) = n0; (x1_) = n1; (x2_) = n2; (x3_) = n3;                        \
    } while (0)

// ---------------------------------------------------------------------------
// Phase 1: per-chunk drive vectors (zero IC replay), fully parallel
// ---------------------------------------------------------------------------
__global__ void phase1_kernel(const float2* __restrict__ u, int nfull) {
    int c = blockIdx.x * blockDim.x + threadIdx.x;
    if (c >= nfull) return;

    float A[16], B[8];
#pragma unroll
    for (int i = 0; i < 16; i++) A[i] = g_A[i];
#pragma unroll
    for (int i = 0; i < 8; i++) B[i] = g_B[i];

    const float2* up = u + (size_t)c * L_CHUNK;
    float x0 = 0.f, x1 = 0.f, x2 = 0.f, x3 = 0.f;
#pragma unroll 4
    for (int i = 0; i < L_CHUNK; i++) {
        float2 uu = up[i];
        AFFINE_STEP(A, B, uu.x, uu.y, x0, x1, x2, x3);
    }
    g_cd[c][0] = x0; g_cd[c][1] = x1; g_cd[c][2] = x2; g_cd[c][3] = x3;
}

// ---------------------------------------------------------------------------
// Phase 2: serial boundary scan x_{c+1} = A^L x_c + d_c (single thread)
// ---------------------------------------------------------------------------
__global__ void phase2_kernel(int nfull) {
    float AL[16];
#pragma unroll
    for (int i = 0; i < 16; i++) AL[i] = g_AL[i];

    float x0 = g_cx[0][0], x1 = g_cx[0][1], x2 = g_cx[0][2], x3 = g_cx[0][3];
#pragma unroll 4
    for (int c = 0; c < nfull; c++) {
        float d0 = g_cd[c][0], d1 = g_cd[c][1], d2 = g_cd[c][2], d3 = g_cd[c][3];
        float n0 = fmaf(AL[0],  x0, AL[1]  * x1) + fmaf(AL[2],  x2, fmaf(AL[3],  x3, d0));
        float n1 = fmaf(AL[4],  x0, AL[5]  * x1) + fmaf(AL[6],  x2, fmaf(AL[7],  x3, d1));
        float n2 = fmaf(AL[8],  x0, AL[9]  * x1) + fmaf(AL[10], x2, fmaf(AL[11], x3, d2));
        float n3 = fmaf(AL[12], x0, AL[13] * x1) + fmaf(AL[14], x2, fmaf(AL[15], x3, d3));
        x0 = n0; x1 = n1; x2 = n2; x3 = n3;
        g_cx[c+1][0] = x0; g_cx[c+1][1] = x1; g_cx[c+1][2] = x2; g_cx[c+1][3] = x3;
    }
}

// ---------------------------------------------------------------------------
// Phase 3: replay each chunk from its known start state, write outputs
// ---------------------------------------------------------------------------
__global__ void phase3_kernel(const float2* __restrict__ u,
                              float2* __restrict__ out,
                              int T, int nchunk) {
    int c = blockIdx.x * blockDim.x + threadIdx.x;
    if (c >= nchunk) return;

    float A[16], B[8];
#pragma unroll
    for (int i = 0; i < 16; i++) A[i] = g_A[i];
#pragma unroll
    for (int i = 0; i < 8; i++) B[i] = g_B[i];

    float x0 = g_cx[c][0], x1 = g_cx[c][1], x2 = g_cx[c][2], x3 = g_cx[c][3];
    int base = c * L_CHUNK;
    int len = T - base;
    if (len > L_CHUNK) len = L_CHUNK;
    const float2* up = u + base;
    float2* op = out + base;
#pragma unroll 4
    for (int i = 0; i < len; i++) {
        float2 uu = up[i];
        AFFINE_STEP(A, B, uu.x, uu.y, x0, x1, x2, x3);
        op[i] = make_float2(x0, x1);   // positions after the step
    }
}

// ---------------------------------------------------------------------------
// Launch
// ---------------------------------------------------------------------------
extern "C" void kernel_launch(void* const* d_in, const int* in_sizes, int n_in,
                              void* d_out, int out_size) {
    const float* u  = (const float*)d_in[0];
    const float* M  = (const float*)d_in[1];
    const float* C  = (const float*)d_in[2];
    const float* K  = (const float*)d_in[3];
    const float* x0 = (const float*)d_in[4];
    const float* dt = (const float*)d_in[5];
    float* out = (float*)d_out;

    int T = in_sizes[0] / 2;
    int nchunk = (T + L_CHUNK - 1) / L_CHUNK;
    int nfull  = nchunk - 1;   // chunks whose drive vector is needed

    setup_kernel<<<1, 1>>>(M, C, K, x0, dt, L_CHUNK);
    if (nfull > 0)
        phase1_kernel<<<(nfull + 127) / 128, 128>>>((const float2*)u, nfull);
    phase2_kernel<<<1, 1>>>(nfull);
    phase3_kernel<<<(nchunk + 127) / 128, 128>>>((const float2*)u, (float2*)out,
                                                 T, nchunk);
}

// round 3
// speedup vs baseline: 4.3168x; 4.3168x over previous
#include <cuda_runtime.h>
#include <cuda_bf16.h>

// Blocked affine-scan RK4 integrator, v2.1 (fixes phase3 half-tile store bug).
// x_{t+1} = A x_t + B u_t exactly (linear system, RK4 step).
//   setup : fp32 basis-probe for A,B; cooperative matrix powers A^L, (A^L)^q, (A^L)^r.
//   phase1: per-chunk drive vectors (smem-staged coalesced loads).
//   phase2: hierarchical boundary scan (one 32-thread block).
//   phase3: per-chunk replay with smem-staged coalesced loads AND stores.

#define L_CHUNK 128
#define TILE 16
#define NT (L_CHUNK / TILE)      // 8 tiles per chunk
#define CPB 32                   // chunks per block (one warp)
#define MAX_CHUNKS 4096

__device__ float g_A[16];
__device__ float g_B[8];
__device__ float g_M[16];        // A^L
__device__ float g_Mq[16];       // (A^L)^q
__device__ float g_Mr[16];       // (A^L)^r
__device__ float g_cd[MAX_CHUNKS][4];      // per-chunk drive vectors
__device__ float g_cx[MAX_CHUNKS + 1][4];  // chunk start states

// ---------------------------------------------------------------------------
// fp32 RK4 step mirroring the reference arithmetic (setup-only)
// ---------------------------------------------------------------------------
struct FSys { float Cm[4], Km[4], Md[2], dt; };

__device__ void fstep(const FSys& m, float s[4], float u0, float u1) {
    float dt = m.dt;
    float y0 = s[0], y1 = s[1], v0 = s[2], v1 = s[3];
#define ACC(z0, z1, w0, w1, a0, a1)                                             \
    a0 = (u0 - (m.Cm[0]*(w0) + m.Cm[1]*(w1)) - (m.Km[0]*(z0) + m.Km[1]*(z1))) / m.Md[0]; \
    a1 = (u1 - (m.Cm[2]*(w0) + m.Cm[3]*(w1)) - (m.Km[2]*(z0) + m.Km[3]*(z1))) / m.Md[1];
    float k1a, k1b; ACC(y0, y1, v0, v1, k1a, k1b);
    float y2a = y0 + v0*dt*0.5f, y2b = y1 + v1*dt*0.5f;
    float v2a = v0 + k1a*dt*0.5f, v2b = v1 + k1b*dt*0.5f;
    float k2a, k2b; ACC(y2a, y2b, v2a, v2b, k2a, k2b);
    float y3a = y0 + v2a*dt*0.5f, y3b = y1 + v2b*dt*0.5f;
    float v3a = v0 + k2a*dt*0.5f, v3b = v1 + k2b*dt*0.5f;
    float k3a, k3b; ACC(y3a, y3b, v3a, v3b, k3a, k3b);
    float y4a = y0 + v3a*dt, y4b = y1 + v3b*dt;
    float v4a = v0 + k3a*dt, v4b = v1 + k3b*dt;
    float k4a, k4b; ACC(y4a, y4b, v4a, v4b, k4a, k4b);
    (void)y2a; (void)y2b; (void)y3a; (void)y3b; (void)y4a; (void)y4b;
    s[0] = y0 + dt/6.f * (v0 + 2.f*v2a + 2.f*v3a + v4a);
    s[1] = y1 + dt/6.f * (v1 + 2.f*v2b + 2.f*v3b + v4b);
    s[2] = v0 + dt/6.f * (k1a + 2.f*k2a + 2.f*k3a + k4a);
    s[3] = v1 + dt/6.f * (k1b + 2.f*k2b + 2.f*k3b + k4b);
#undef ACC
}

// Cooperative 4x4 matmul (threads 0..15, one element each)
__device__ __forceinline__ void coop_mm(float* R, const float* Pm, const float* Qm, int t) {
    if (t < 16) {
        int i = t >> 2, j = t & 3;
        R[t] = fmaf(Pm[i*4+0], Qm[0*4+j],
               fmaf(Pm[i*4+1], Qm[1*4+j],
               fmaf(Pm[i*4+2], Qm[2*4+j],
                    Pm[i*4+3] * Qm[3*4+j])));
    }
    __syncwarp();
}

// dst = base^e (e >= 1). sP/sQ/sR: shared scratch, distinct from base.
__device__ void coop_pow(float* dst, const float* base, int e,
                         float* sP, float* sQ, float* sR, int t) {
    if (t < 16) {
        sP[t] = (t == 0 || t == 5 || t == 10 || t == 15) ? 1.f : 0.f;
        sQ[t] = base[t];
    }
    __syncwarp();
    while (e) {
        if (e & 1) {
            coop_mm(sR, sP, sQ, t);
            if (t < 16) sP[t] = sR[t];
            __syncwarp();
        }
        e >>= 1;
        if (e) {
            coop_mm(sR, sQ, sQ, t);
            if (t < 16) sQ[t] = sR[t];
            __syncwarp();
        }
    }
    if (t < 16) dst[t] = sP[t];
    __syncwarp();
}

// ---------------------------------------------------------------------------
// Setup: A, B via basis probing; matrix powers; initial state
// ---------------------------------------------------------------------------
__global__ void setup_kernel(const float* __restrict__ M, const float* __restrict__ C,
                             const float* __restrict__ K, const float* __restrict__ x0,
                             const float* __restrict__ dtp, int q, int r) {
    __shared__ float sA[16], sM[16], sP[16], sQ[16], sR[16];
    int t = threadIdx.x;

    FSys m;
    m.Md[0] = M[0]; m.Md[1] = M[1];
    float C0 = C[0], C1 = C[1], C2 = C[2];
    m.Cm[0] = C0 + C1; m.Cm[1] = -C1; m.Cm[2] = -C1; m.Cm[3] = C2 + C1;
    float K0 = K[0], K1 = K[1], K2 = K[2];
    m.Km[0] = K0 + K1; m.Km[1] = -K1; m.Km[2] = -K1; m.Km[3] = K2 + K1;
    m.dt = dtp[0];

    if (t < 4) {                                  // A columns: step(e_t, u=0)
        float s[4] = {0, 0, 0, 0}; s[t] = 1.f;
        fstep(m, s, 0.f, 0.f);
        sA[0*4 + t] = s[0]; sA[1*4 + t] = s[1]; sA[2*4 + t] = s[2]; sA[3*4 + t] = s[3];
    }
    if (t < 2) {                                  // B columns: step(0, e_t)
        float s[4] = {0, 0, 0, 0};
        fstep(m, s, t == 0 ? 1.f : 0.f, t == 1 ? 1.f : 0.f);
        g_B[0*2 + t] = s[0]; g_B[1*2 + t] = s[1]; g_B[2*2 + t] = s[2]; g_B[3*2 + t] = s[3];
    }
    __syncwarp();
    if (t < 16) g_A[t] = sA[t];
    __syncwarp();

    coop_pow(sM, sA, L_CHUNK, sP, sQ, sR, t);     // M = A^L
    if (t < 16) g_M[t] = sM[t];
    __syncwarp();
    coop_pow(g_Mq, sM, q, sP, sQ, sR, t);         // M^q
    coop_pow(g_Mr, sM, r, sP, sQ, sR, t);         // M^r

    if (t == 0) {                                 // x0 layout [y1,v1,y2,v2] -> [y1,y2,v1,v2]
        g_cx[0][0] = x0[0];
        g_cx[0][1] = x0[2];
        g_cx[0][2] = x0[1];
        g_cx[0][3] = x0[3];
    }
}

// ---------------------------------------------------------------------------
// x <- Am x + d  (tree-reduced, 12-cycle critical path)
// ---------------------------------------------------------------------------
#define MATVEC4(Am, d0, d1, d2, d3, x0_, x1_, x2_, x3_)                        \
    do {                                                                       \
        float n0 = fmaf((Am)[0],  (x0_), (Am)[1]  * (x1_)) +                   \
                   fmaf((Am)[2],  (x2_), fmaf((Am)[3],  (x3_), (d0)));         \
        float n1 = fmaf((Am)[4],  (x0_), (Am)[5]  * (x1_)) +                   \
                   fmaf((Am)[6],  (x2_), fmaf((Am)[7],  (x3_), (d1)));         \
        float n2 = fmaf((Am)[8],  (x0_), (Am)[9]  * (x1_)) +                   \
                   fmaf((Am)[10], (x2_), fmaf((Am)[11], (x3_), (d2)));         \
        float n3 = fmaf((Am)[12], (x0_), (Am)[13] * (x1_)) +                   \
                   fmaf((Am)[14], (x2_), fmaf((Am)[15], (x3_), (d3)));         \
        (x0_) = n0; (x1_) = n1; (x2_) = n2; (x3_) = n3;                        \
    } while (0)

#define AFFINE_STEP(A, B, ux, uy, x0_, x1_, x2_, x3_)                          \
    do {                                                                       \
        float r0 = fmaf((B)[0], (ux), (B)[1] * (uy));                          \
        float r1 = fmaf((B)[2], (ux), (B)[3] * (uy));                          \
        float r2 = fmaf((B)[4], (ux), (B)[5] * (uy));                          \
        float r3 = fmaf((B)[6], (ux), (B)[7] * (uy));                          \
        MATVEC4(A, r0, r1, r2, r3, x0_, x1_, x2_, x3_);                        \
    } while (0)

// Coalesced tile prefetch: 8 float4 per thread covering 32 rows x 8 float4
#define LOAD_TILE(pre, u4, c0, k, nf4)                                         \
    do {                                                                       \
        _Pragma("unroll")                                                      \
        for (int j = 0; j < 8; j++) {                                          \
            int idx = threadIdx.x + 32 * j;                                    \
            int row = idx >> 3, col = idx & 7;                                 \
            long G = (long)(c0 + row) * (L_CHUNK / 2) + (k) * (TILE / 2) + col;\
            pre[j] = (G < (nf4)) ? (u4)[G] : make_float4(0.f, 0.f, 0.f, 0.f);  \
        }                                                                      \
    } while (0)

#define STORE_TILE_SMEM(pre, s_in)                                             \
    do {                                                                       \
        _Pragma("unroll")                                                      \
        for (int j = 0; j < 8; j++) {                                          \
            int idx = threadIdx.x + 32 * j;                                    \
            int row = idx >> 3, col = idx & 7;                                 \
            s_in[row][2*col]   = make_float2(pre[j].x, pre[j].y);              \
            s_in[row][2*col+1] = make_float2(pre[j].z, pre[j].w);              \
        }                                                                      \
    } while (0)

// ---------------------------------------------------------------------------
// Phase 1: per-chunk drive vectors (zero IC), smem-staged coalesced loads
// ---------------------------------------------------------------------------
__global__ void phase1_kernel(const float4* __restrict__ u4, int P, long nf4) {
    __shared__ float2 s_in[CPB][TILE + 1];
    int t = threadIdx.x;
    int c0 = blockIdx.x * CPB;
    int c = c0 + t;

    float A[16], B[8];
#pragma unroll
    for (int i = 0; i < 16; i++) A[i] = g_A[i];
#pragma unroll
    for (int i = 0; i < 8; i++) B[i] = g_B[i];

    float x0 = 0.f, x1 = 0.f, x2 = 0.f, x3 = 0.f;
    float4 pre[8];
    LOAD_TILE(pre, u4, c0, 0, nf4);

#pragma unroll
    for (int k = 0; k < NT; k++) {
        __syncwarp();
        STORE_TILE_SMEM(pre, s_in);
        __syncwarp();
        if (k + 1 < NT) LOAD_TILE(pre, u4, c0, k + 1, nf4);
#pragma unroll
        for (int i = 0; i < TILE; i++) {
            float2 uu = s_in[t][i];
            AFFINE_STEP(A, B, uu.x, uu.y, x0, x1, x2, x3);
        }
    }
    if (c < P) {
        g_cd[c][0] = x0; g_cd[c][1] = x1; g_cd[c][2] = x2; g_cd[c][3] = x3;
    }
}

// ---------------------------------------------------------------------------
// Phase 2: hierarchical boundary scan, one 32-thread block
//   a) thread t scans drives [t*q, min(P,(t+1)q)) with matrix M
//   b) thread 0 combines partials with M^q (last active uses M^r)
//   c) thread t replays its range, storing all chunk start states
// ---------------------------------------------------------------------------
__global__ void phase2_kernel(int P, int q, int nact) {
    __shared__ float s_e[32][4];
    __shared__ float s_x[32][4];
    int t = threadIdx.x;

    float Mm[16];
#pragma unroll
    for (int i = 0; i < 16; i++) Mm[i] = g_M[i];

    int lo = t * q;
    int hi = lo + q; if (hi > P) hi = P;

    float e0 = 0.f, e1 = 0.f, e2 = 0.f, e3 = 0.f;
#pragma unroll 4
    for (int j = lo; j < hi; j++) {
        float d0 = g_cd[j][0], d1 = g_cd[j][1], d2 = g_cd[j][2], d3 = g_cd[j][3];
        MATVEC4(Mm, d0, d1, d2, d3, e0, e1, e2, e3);
    }
    s_e[t][0] = e0; s_e[t][1] = e1; s_e[t][2] = e2; s_e[t][3] = e3;
    __syncwarp();

    if (t == 0) {
        float Mq[16], Mr[16];
#pragma unroll
        for (int i = 0; i < 16; i++) { Mq[i] = g_Mq[i]; Mr[i] = g_Mr[i]; }
        float x0 = g_cx[0][0], x1 = g_cx[0][1], x2 = g_cx[0][2], x3 = g_cx[0][3];
        for (int tt = 0; tt < nact; tt++) {
            s_x[tt][0] = x0; s_x[tt][1] = x1; s_x[tt][2] = x2; s_x[tt][3] = x3;
            float d0 = s_e[tt][0], d1 = s_e[tt][1], d2 = s_e[tt][2], d3 = s_e[tt][3];
            const float* MM = (tt == nact - 1) ? Mr : Mq;
            MATVEC4(MM, d0, d1, d2, d3, x0, x1, x2, x3);
        }
    }
    __syncwarp();

    if (lo < P) {
        float x0 = s_x[t][0], x1 = s_x[t][1], x2 = s_x[t][2], x3 = s_x[t][3];
#pragma unroll 4
        for (int j = lo; j < hi; j++) {
            float d0 = g_cd[j][0], d1 = g_cd[j][1], d2 = g_cd[j][2], d3 = g_cd[j][3];
            MATVEC4(Mm, d0, d1, d2, d3, x0, x1, x2, x3);
            g_cx[j+1][0] = x0; g_cx[j+1][1] = x1; g_cx[j+1][2] = x2; g_cx[j+1][3] = x3;
        }
    }
}

// ---------------------------------------------------------------------------
// Phase 3: replay chunks from known start states; staged loads AND stores
// ---------------------------------------------------------------------------
__global__ void phase3_kernel(const float4* __restrict__ u4, float4* __restrict__ out4,
                              int nchunk, long nf4) {
    __shared__ float2 s_in[CPB][TILE + 1];
    __shared__ float2 s_out[CPB][TILE + 1];
    int t = threadIdx.x;
    int c0 = blockIdx.x * CPB;
    int c = c0 + t;

    float A[16], B[8];
#pragma unroll
    for (int i = 0; i < 16; i++) A[i] = g_A[i];
#pragma unroll
    for (int i = 0; i < 8; i++) B[i] = g_B[i];

    float x0 = 0.f, x1 = 0.f, x2 = 0.f, x3 = 0.f;
    if (c < nchunk) {
        x0 = g_cx[c][0]; x1 = g_cx[c][1]; x2 = g_cx[c][2]; x3 = g_cx[c][3];
    }

    float4 pre[8];
    LOAD_TILE(pre, u4, c0, 0, nf4);

#pragma unroll
    for (int k = 0; k < NT; k++) {
        __syncwarp();
        STORE_TILE_SMEM(pre, s_in);
        __syncwarp();
        if (k + 1 < NT) LOAD_TILE(pre, u4, c0, k + 1, nf4);
#pragma unroll
        for (int i = 0; i < TILE; i++) {
            float2 uu = s_in[t][i];
            AFFINE_STEP(A, B, uu.x, uu.y, x0, x1, x2, x3);
            s_out[t][i] = make_float2(x0, x1);
        }
        __syncwarp();
        // coalesced store of the FULL output tile: 256 float4 = 32 thr x 8 iters
#pragma unroll
        for (int j = 0; j < 8; j++) {
            int idx = t + 32 * j;
            int row = idx >> 3, col4 = idx & 7;
            long G = (long)(c0 + row) * (L_CHUNK / 2) + k * (TILE / 2) + col4;
            if (G < nf4) {
                float2 a = s_out[row][2*col4];
                float2 b = s_out[row][2*col4+1];
                out4[G] = make_float4(a.x, a.y, b.x, b.y);
            }
        }
    }
}

// ---------------------------------------------------------------------------
// Launch
// ---------------------------------------------------------------------------
extern "C" void kernel_launch(void* const* d_in, const int* in_sizes, int n_in,
                              void* d_out, int out_size) {
    const float* u  = (const float*)d_in[0];
    const float* M  = (const float*)d_in[1];
    const float* C  = (const float*)d_in[2];
    const float* K  = (const float*)d_in[3];
    const float* x0 = (const float*)d_in[4];
    const float* dt = (const float*)d_in[5];

    int T = in_sizes[0] / 2;
    int nchunk = (T + L_CHUNK - 1) / L_CHUNK;
    int P = nchunk - 1;                       // drives needed for chunks 0..P-1
    int q = (P + 31) / 32; if (q < 1) q = 1;
    int nact = (P + q - 1) / q;               // active scan threads
    int r = P - (nact - 1) * q;               // last active thread's range
    if (r < 1) r = 1;
    long nf4 = (long)(2 * T) / 4;             // total float4 elements in u / out

    setup_kernel<<<1, 32>>>(M, C, K, x0, dt, q, r);
    if (P > 0) {
        int nb1 = (P + CPB - 1) / CPB;
        phase1_kernel<<<nb1, 32>>>((const float4*)u, P, nf4);
        phase2_kernel<<<1, 32>>>(P, q, nact);
    }
    int nb3 = (nchunk + CPB - 1) / CPB;
    phase3_kernel<<<nb3, 32>>>((const float4*)u, (float4*)d_out, nchunk, nf4);
}